// round 2
// baseline (speedup 1.0000x reference)
#include <cuda_runtime.h>
#include <cstddef>

#define BATCH 4096
#define LDIM 64
#define DDIM 256
#define MDIM 20
#define R1 32
#define R2 32
#define XPAD 260   // padded row stride for conflict-free LDS.128

// ---------------- scratch (no allocations allowed) ----------------
__device__ float g_Wt[3 * MDIM * DDIM];             // transposed weights [proj][m][d]
__device__ float g_qs[(size_t)LDIM * BATCH * MDIM]; // [l][b][m]
__device__ float g_kvs[LDIM * MDIM * MDIM];
__device__ float g_ks_sum[LDIM * MDIM];
__device__ float g_vs_sum[LDIM * MDIM];
__device__ float g_scal[4];                         // sum_q, ssq_q, sum_k, ssq_k
__device__ float g_P[(size_t)LDIM * MDIM * DDIM];   // kvs @ Wp
__device__ float g_C[LDIM * DDIM];                  // vs_sum @ Wp

// ---------------- kernel 0: zero reductions + transpose weights ----------------
__global__ __launch_bounds__(256) void k_init(const float* __restrict__ Wk,
                                              const float* __restrict__ Wq,
                                              const float* __restrict__ Wv) {
    int i = blockIdx.x * 256 + threadIdx.x;
    if (i < 3 * MDIM * DDIM) {
        int p = i / (MDIM * DDIM);
        int rem = i % (MDIM * DDIM);
        int m = rem / DDIM, d = rem % DDIM;
        const float* W = (p == 0) ? Wk : ((p == 1) ? Wq : Wv);
        g_Wt[i] = W[d * MDIM + m];
    }
    if (i < LDIM * MDIM * MDIM) g_kvs[i] = 0.f;
    if (i < LDIM * MDIM) { g_ks_sum[i] = 0.f; g_vs_sum[i] = 0.f; }
    if (i < 4) g_scal[i] = 0.f;
}

// ---------------- kernel 1: projections + reductions ----------------
// Block: 256 threads, 32 rows (one l, b-chunk). Warp w, lane r:
// lane computes row r; warp covers m in {w, w+8, w+16 (if <20)}.
extern __shared__ float smem1[];

__global__ __launch_bounds__(256) void k_pass1(const float* __restrict__ key,
                                               const float* __restrict__ query,
                                               const float* __restrict__ value,
                                               const float* __restrict__ bk,
                                               const float* __restrict__ bq,
                                               const float* __restrict__ bv) {
    float* x_s  = smem1;                    // [32][260]
    float* wt_s = x_s + R1 * XPAD;          // [20][256]
    float* kt   = wt_s + MDIM * DDIM;       // [32][20]
    float* qt   = kt + R1 * MDIM;
    float* vt   = qt + R1 * MDIM;
    float* kvp  = vt + R1 * MDIM;           // [8][20][20]
    float* red  = kvp + 8 * MDIM * MDIM;    // [8][4]

    const int tid = threadIdx.x;
    const int w = tid >> 5, lane = tid & 31;
    const int l = blockIdx.y;
    const int b0 = blockIdx.x * R1;

    #pragma unroll 1
    for (int p = 0; p < 3; p++) {
        __syncthreads();
        const float* src  = (p == 0) ? key : ((p == 1) ? query : value);
        const float* bias = (p == 0) ? bk  : ((p == 1) ? bq    : bv);
        // stage transposed weights
        for (int i = tid; i < MDIM * DDIM; i += 256)
            wt_s[i] = g_Wt[p * MDIM * DDIM + i];
        // stage 32 input rows (coalesced float4)
        for (int i = tid; i < R1 * DDIM / 4; i += 256) {
            int r = i >> 6;
            int c = (i & 63) << 2;
            float4 v4 = *reinterpret_cast<const float4*>(
                src + ((size_t)(b0 + r) * LDIM + l) * DDIM + c);
            *reinterpret_cast<float4*>(x_s + r * XPAD + c) = v4;
        }
        __syncthreads();

        const int m0 = w, m1 = w + 8, m2 = w + 16;
        float a0 = __ldg(bias + m0);
        float a1 = __ldg(bias + m1);
        float a2 = (m2 < MDIM) ? __ldg(bias + m2) : 0.f;
        const float* xr  = x_s + lane * XPAD;
        const float* w0p = wt_s + m0 * DDIM;
        const float* w1p = wt_s + m1 * DDIM;
        const float* w2p = wt_s + ((m2 < MDIM) ? m2 : 0) * DDIM;
        #pragma unroll 8
        for (int d = 0; d < DDIM; d += 4) {
            float4 xv = *reinterpret_cast<const float4*>(xr + d);
            float4 u0 = *reinterpret_cast<const float4*>(w0p + d);
            a0 += xv.x * u0.x + xv.y * u0.y + xv.z * u0.z + xv.w * u0.w;
            float4 u1 = *reinterpret_cast<const float4*>(w1p + d);
            a1 += xv.x * u1.x + xv.y * u1.y + xv.z * u1.z + xv.w * u1.w;
            float4 u2 = *reinterpret_cast<const float4*>(w2p + d);
            a2 += xv.x * u2.x + xv.y * u2.y + xv.z * u2.z + xv.w * u2.w;
        }
        float* ot = (p == 0) ? kt : ((p == 1) ? qt : vt);
        ot[lane * MDIM + m0] = a0;
        ot[lane * MDIM + m1] = a1;
        if (m2 < MDIM) ot[lane * MDIM + m2] = a2;
    }
    __syncthreads();

    // store qs (layout [l][b][m] -> fully linear per block)
    for (int i = tid; i < R1 * MDIM; i += 256)
        g_qs[((size_t)l * BATCH + b0) * MDIM + i] = qt[i];

    // kvs partials: warp w owns rows 4w..4w+3, lanes 0..19 own m
    if (lane < MDIM) {
        float acc[MDIM];
        #pragma unroll
        for (int j = 0; j < MDIM; j++) acc[j] = 0.f;
        #pragma unroll
        for (int rr = 0; rr < 4; rr++) {
            int r = w * 4 + rr;
            float km = kt[r * MDIM + lane];
            #pragma unroll
            for (int j = 0; j < MDIM; j++) acc[j] += km * vt[r * MDIM + j];
        }
        #pragma unroll
        for (int j = 0; j < MDIM; j++) kvp[(w * MDIM + lane) * MDIM + j] = acc[j];
    }

    // scalar partials (sum / sumsq of raw ks, qs)
    float sk = 0.f, ssk = 0.f, sq = 0.f, ssq = 0.f;
    for (int i = tid; i < R1 * MDIM; i += 256) {
        float kv_ = kt[i], qv_ = qt[i];
        sk += kv_; ssk += kv_ * kv_; sq += qv_; ssq += qv_ * qv_;
    }
    #pragma unroll
    for (int off = 16; off; off >>= 1) {
        sk  += __shfl_down_sync(0xffffffffu, sk,  off);
        ssk += __shfl_down_sync(0xffffffffu, ssk, off);
        sq  += __shfl_down_sync(0xffffffffu, sq,  off);
        ssq += __shfl_down_sync(0xffffffffu, ssq, off);
    }
    if (lane == 0) { red[w*4+0] = sk; red[w*4+1] = ssk; red[w*4+2] = sq; red[w*4+3] = ssq; }
    __syncthreads();

    if (tid < 4) {
        float s = 0.f;
        #pragma unroll
        for (int ww = 0; ww < 8; ww++) s += red[ww * 4 + tid];
        // tid: 0=sk->scal[2], 1=ssk->scal[3], 2=sq->scal[0], 3=ssq->scal[1]
        atomicAdd(&g_scal[(tid + 2) & 3], s);
    }
    for (int i = tid; i < MDIM * MDIM; i += 256) {
        float s = 0.f;
        #pragma unroll
        for (int ww = 0; ww < 8; ww++) s += kvp[ww * MDIM * MDIM + i];
        atomicAdd(&g_kvs[l * MDIM * MDIM + i], s);
    }
    if (tid < MDIM) {
        float s1 = 0.f, s2 = 0.f;
        #pragma unroll
        for (int r = 0; r < R1; r++) { s1 += kt[r * MDIM + tid]; s2 += vt[r * MDIM + tid]; }
        atomicAdd(&g_ks_sum[l * MDIM + tid], s1);
        atomicAdd(&g_vs_sum[l * MDIM + tid], s2);
    }
}

// ---------------- kernel 2: P[l] = kvs[l] @ Wp, C[l] = vs_sum[l] @ Wp ----------------
__global__ __launch_bounds__(256) void k_mid(const float* __restrict__ Wp) {
    __shared__ float kvs_s[MDIM * MDIM];
    __shared__ float vsum_s[MDIM];
    int l = blockIdx.x, tid = threadIdx.x;
    for (int i = tid; i < MDIM * MDIM; i += 256) kvs_s[i] = g_kvs[l * MDIM * MDIM + i];
    if (tid < MDIM) vsum_s[tid] = g_vs_sum[l * MDIM + tid];
    __syncthreads();
    int d = tid;
    float wp[MDIM];
    #pragma unroll
    for (int m2 = 0; m2 < MDIM; m2++) wp[m2] = __ldg(Wp + m2 * DDIM + d);
    float c = 0.f;
    #pragma unroll
    for (int m2 = 0; m2 < MDIM; m2++) c += vsum_s[m2] * wp[m2];
    g_C[l * DDIM + d] = c;
    #pragma unroll 4
    for (int m = 0; m < MDIM; m++) {
        float s = 0.f;
        #pragma unroll
        for (int m2 = 0; m2 < MDIM; m2++) s += kvs_s[m * MDIM + m2] * wp[m2];
        g_P[((size_t)l * MDIM + m) * DDIM + d] = s;
    }
}

// ---------------- kernel 3: output ----------------
// out[d] = (alpha * (qs . P[l][:,d]) + C[l][d]) / (alpha * (qs . ks_sum[l]) + B) + bp[d]
__global__ __launch_bounds__(256) void k_pass2(float* __restrict__ out,
                                               const float* __restrict__ bp) {
    __shared__ __align__(16) float P_s[MDIM * DDIM];
    __shared__ __align__(16) float C_s[DDIM];
    __shared__ __align__(16) float bp_s[DDIM];
    __shared__ float ksum_s[MDIM];
    __shared__ float qs_s[R2 * MDIM];
    const int tid = threadIdx.x, w = tid >> 5, lane = tid & 31;
    const int l = blockIdx.y, b0 = blockIdx.x * R2;

    for (int i = tid; i < MDIM * DDIM; i += 256) P_s[i] = g_P[(size_t)l * MDIM * DDIM + i];
    if (tid < DDIM) { C_s[tid] = g_C[l * DDIM + tid]; bp_s[tid] = bp[tid]; }
    if (tid < MDIM) ksum_s[tid] = g_ks_sum[l * MDIM + tid];
    for (int i = tid; i < R2 * MDIM; i += 256)
        qs_s[i] = g_qs[((size_t)l * BATCH + b0) * MDIM + i];

    float sq = g_scal[0], ssq = g_scal[1], sk = g_scal[2], ssk = g_scal[3];
    float alpha = (sq != 0.f && sk != 0.f) ? rsqrtf(ssq) * rsqrtf(ssk) : 1.f;
    __syncthreads();

    const int r0 = w * 4;
    const int dbase = lane * 4;
    float4 acc[4][2];
    #pragma unroll
    for (int rr = 0; rr < 4; rr++)
        #pragma unroll
        for (int j = 0; j < 2; j++) acc[rr][j] = make_float4(0.f, 0.f, 0.f, 0.f);
    float s0 = 0.f, s1 = 0.f, s2 = 0.f, s3 = 0.f;

    #pragma unroll
    for (int m = 0; m < MDIM; m++) {
        float q0 = qs_s[(r0 + 0) * MDIM + m];
        float q1 = qs_s[(r0 + 1) * MDIM + m];
        float q2 = qs_s[(r0 + 2) * MDIM + m];
        float q3 = qs_s[(r0 + 3) * MDIM + m];
        float km = ksum_s[m];
        s0 += q0 * km; s1 += q1 * km; s2 += q2 * km; s3 += q3 * km;
        #pragma unroll
        for (int j = 0; j < 2; j++) {
            float4 pv = *reinterpret_cast<const float4*>(&P_s[m * DDIM + dbase + j * 128]);
            acc[0][j].x += q0 * pv.x; acc[0][j].y += q0 * pv.y; acc[0][j].z += q0 * pv.z; acc[0][j].w += q0 * pv.w;
            acc[1][j].x += q1 * pv.x; acc[1][j].y += q1 * pv.y; acc[1][j].z += q1 * pv.z; acc[1][j].w += q1 * pv.w;
            acc[2][j].x += q2 * pv.x; acc[2][j].y += q2 * pv.y; acc[2][j].z += q2 * pv.z; acc[2][j].w += q2 * pv.w;
            acc[3][j].x += q3 * pv.x; acc[3][j].y += q3 * pv.y; acc[3][j].z += q3 * pv.z; acc[3][j].w += q3 * pv.w;
        }
    }

    float sv[4] = {s0, s1, s2, s3};
    #pragma unroll
    for (int rr = 0; rr < 4; rr++) {
        float inv = 1.f / (alpha * sv[rr] + (float)BATCH);
        float ai = alpha * inv;
        size_t base = ((size_t)(b0 + r0 + rr) * LDIM + l) * DDIM;
        #pragma unroll
        for (int j = 0; j < 2; j++) {
            int d = dbase + j * 128;
            float4 c4 = *reinterpret_cast<const float4*>(&C_s[d]);
            float4 b4 = *reinterpret_cast<const float4*>(&bp_s[d]);
            float4 o;
            o.x = acc[rr][j].x * ai + c4.x * inv + b4.x;
            o.y = acc[rr][j].y * ai + c4.y * inv + b4.y;
            o.z = acc[rr][j].z * ai + c4.z * inv + b4.z;
            o.w = acc[rr][j].w * ai + c4.w * inv + b4.w;
            *reinterpret_cast<float4*>(out + base + d) = o;
        }
    }
}

// ---------------- launch ----------------
extern "C" void kernel_launch(void* const* d_in, const int* in_sizes, int n_in,
                              void* d_out, int out_size) {
    const float* key   = (const float*)d_in[0];
    const float* value = (const float*)d_in[1];
    const float* query = (const float*)d_in[2];
    const float* Wk = (const float*)d_in[3];
    const float* bk = (const float*)d_in[4];
    const float* Wq = (const float*)d_in[5];
    const float* bq = (const float*)d_in[6];
    const float* Wv = (const float*)d_in[7];
    const float* bv = (const float*)d_in[8];
    const float* Wp = (const float*)d_in[9];
    const float* bp = (const float*)d_in[10];
    float* out = (float*)d_out;
    (void)in_sizes; (void)n_in; (void)out_size;

    const int smem1_bytes = (R1 * XPAD + MDIM * DDIM + 3 * R1 * MDIM +
                             8 * MDIM * MDIM + 32) * (int)sizeof(float); // 74368
    cudaFuncSetAttribute(k_pass1, cudaFuncAttributeMaxDynamicSharedMemorySize, smem1_bytes);

    k_init<<<104, 256>>>(Wk, Wq, Wv);
    k_pass1<<<dim3(BATCH / R1, LDIM), 256, smem1_bytes>>>(key, query, value, bk, bq, bv);
    k_mid<<<LDIM, 256>>>(Wp);
    k_pass2<<<dim3(BATCH / R2, LDIM), 256>>>(out, bp);
}